// round 3
// baseline (speedup 1.0000x reference)
#include <cuda_runtime.h>
#include <cstdint>

// Problem dims
#define B_  2
#define C_  4
#define D_  64
#define H_  160
#define W_  160
#define HW_ (H_ * W_)            // 25600
#define NSLICE (B_ * C_ * D_)    // 512
#define NVOX_PER_CH (B_ * D_ * H_ * W_)  // 3,276,800

// Gaussian window (k=11, sigma=1.5), normalized, symmetric. Literals so ptxas
// uses FFMA-imm (rt=1).
#define GW0 0.00102838f
#define GW1 0.00759876f
#define GW2 0.03600077f
#define GW3 0.10936069f
#define GW4 0.21300554f
#define GW5 0.26601173f

#define SSIM_C1 1.0e-4f
#define SSIM_C2 9.0e-4f

// Scratch: 5 fields x [B,C,D,H,W] fp32 = 262 MB (static device array; no allocs)
#define FIELD_STRIDE ((long long)NSLICE * HW_)  // 13,107,200
__device__ float g_tmp[5LL * FIELD_STRIDE];
__device__ float g_acc[C_];

// 11-tap symmetric conv over v[J..J+10], all-constant indices (template J so
// the register array never demotes to local memory).
template <int J>
__device__ __forceinline__ float conv11(const float (&v)[14]) {
    float s = v[J + 0] * GW0;
    s = fmaf(v[J + 1], GW1, s);
    s = fmaf(v[J + 2], GW2, s);
    s = fmaf(v[J + 3], GW3, s);
    s = fmaf(v[J + 4], GW4, s);
    s = fmaf(v[J + 5], GW5, s);
    s = fmaf(v[J + 6], GW4, s);
    s = fmaf(v[J + 7], GW3, s);
    s = fmaf(v[J + 8], GW2, s);
    s = fmaf(v[J + 9], GW1, s);
    s = fmaf(v[J + 10], GW0, s);
    return s;
}

__device__ __forceinline__ float conv11r(const float (&v)[11]) {
    float s = v[0] * GW0;
    s = fmaf(v[1], GW1, s);
    s = fmaf(v[2], GW2, s);
    s = fmaf(v[3], GW3, s);
    s = fmaf(v[4], GW4, s);
    s = fmaf(v[5], GW5, s);
    s = fmaf(v[6], GW4, s);
    s = fmaf(v[7], GW3, s);
    s = fmaf(v[8], GW2, s);
    s = fmaf(v[9], GW1, s);
    s = fmaf(v[10], GW0, s);
    return s;
}

// ---------------------------------------------------------------------------
// Pass A: per D-slice, separable W-then-H conv of the 5 fields
//   fields: x1, x2, x1*x1, x2*x2, x1*x2
// Tile: 32x32 outputs, halo 5 -> 42x42 input tile in smem.
// ---------------------------------------------------------------------------
#define TS 32
#define HALO 5
#define TIN 42  // TS + 2*HALO

__global__ void __launch_bounds__(256) passA_kernel(
    const float* __restrict__ img1, const float* __restrict__ img2) {
    __shared__ float s1[TIN][TIN + 1];        // stride 43: conflict-free
    __shared__ float s2[TIN][TIN + 1];
    __shared__ float mid[5][TIN][TS + 1];     // stride 33: conflict-free

    const int slice = blockIdx.z;             // b*C*D + c*D + d
    const int ty0 = blockIdx.y * TS;
    const int tx0 = blockIdx.x * TS;
    const int tid = threadIdx.x;

    const float* p1 = img1 + (long long)slice * HW_;
    const float* p2 = img2 + (long long)slice * HW_;

    // Load 42x42 halo tiles (zero padding outside image)
    for (int i = tid; i < TIN * TIN; i += 256) {
        int y = i / TIN, x = i - y * TIN;
        int gy = ty0 + y - HALO;
        int gx = tx0 + x - HALO;
        bool ok = ((unsigned)gy < (unsigned)H_) && ((unsigned)gx < (unsigned)W_);
        float a = 0.f, b = 0.f;
        if (ok) {
            int gi = gy * W_ + gx;
            a = p1[gi];
            b = p2[gi];
        }
        s1[y][x] = a;
        s2[y][x] = b;
    }
    __syncthreads();

    // W-direction conv: 42 rows x 32 cols of mid, each thread does 4 consecutive x
    // work items: 42 rows * 8 quads = 336
    for (int i = tid; i < TIN * 8; i += 256) {
        int y = i >> 3;
        int x0 = (i & 7) << 2;
        float v1[14], v2[14], q11[14], q22[14], q12[14];
#pragma unroll
        for (int t = 0; t < 14; t++) {
            float a = s1[y][x0 + t];
            float b = s2[y][x0 + t];
            v1[t] = a;
            v2[t] = b;
            q11[t] = a * a;
            q22[t] = b * b;
            q12[t] = a * b;
        }
#define STORE4(F, ARR)                               \
        mid[F][y][x0 + 0] = conv11<0>(ARR);          \
        mid[F][y][x0 + 1] = conv11<1>(ARR);          \
        mid[F][y][x0 + 2] = conv11<2>(ARR);          \
        mid[F][y][x0 + 3] = conv11<3>(ARR);
        STORE4(0, v1)
        STORE4(1, v2)
        STORE4(2, q11)
        STORE4(3, q22)
        STORE4(4, q12)
#undef STORE4
    }
    __syncthreads();

    // H-direction conv: 32x32 outputs, each thread does 4 consecutive y at one x
    {
        int x = tid & 31;
        int y0 = (tid >> 5) << 2;  // 0..28 step 4
        long long obase = (long long)slice * HW_ + (long long)(ty0 + y0) * W_ + (tx0 + x);
#pragma unroll
        for (int f = 0; f < 5; f++) {
            float v[14];
#pragma unroll
            for (int t = 0; t < 14; t++) v[t] = mid[f][y0 + t][x];
            float* op = g_tmp + (long long)f * FIELD_STRIDE + obase;
            op[0 * W_] = conv11<0>(v);
            op[1 * W_] = conv11<1>(v);
            op[2 * W_] = conv11<2>(v);
            op[3 * W_] = conv11<3>(v);
        }
    }
}

// ---------------------------------------------------------------------------
// Pass B: D-direction conv (register ring, each plane loaded once) fused with
// SSIM map + per-channel mean reduction.
// Grid: one block per (b,c,y) = 1280 blocks, 160 threads (one per x).
// ---------------------------------------------------------------------------
__global__ void __launch_bounds__(160) passB_kernel() {
    const int bid = blockIdx.x;          // (b*C + c)*H + y
    const int y = bid % H_;
    const int bc = bid / H_;             // b*C + c
    const int c = bc % C_;
    const int x = threadIdx.x;           // 0..159

    const long long off0 = (long long)bc * D_ * HW_ + (long long)y * W_ + x;
    const float* t0 = g_tmp + 0LL * FIELD_STRIDE + off0;
    const float* t1 = g_tmp + 1LL * FIELD_STRIDE + off0;
    const float* t2 = g_tmp + 2LL * FIELD_STRIDE + off0;
    const float* t3 = g_tmp + 3LL * FIELD_STRIDE + off0;
    const float* t4 = g_tmp + 4LL * FIELD_STRIDE + off0;

    float r1[11], r2[11], r11[11], r22[11], r12[11];
    // Preload planes d = -5..5 (zeros out of range)
#pragma unroll
    for (int k = 0; k < 11; k++) {
        int d = k - 5;
        bool ok = (unsigned)d < (unsigned)D_;
        long long o = (long long)d * HW_;
        r1[k] = ok ? t0[o] : 0.f;
        r2[k] = ok ? t1[o] : 0.f;
        r11[k] = ok ? t2[o] : 0.f;
        r22[k] = ok ? t3[o] : 0.f;
        r12[k] = ok ? t4[o] : 0.f;
    }

    float acc = 0.f;
    for (int d = 0; d < D_; d++) {
        float mu1 = conv11r(r1);
        float mu2 = conv11r(r2);
        float e11 = conv11r(r11);
        float e22 = conv11r(r22);
        float e12 = conv11r(r12);

        float mu1sq = mu1 * mu1;
        float mu2sq = mu2 * mu2;
        float mu12 = mu1 * mu2;
        float s11 = e11 - mu1sq;
        float s22 = e22 - mu2sq;
        float s12 = e12 - mu12;

        float num = (2.f * mu12 + SSIM_C1) * (2.f * s12 + SSIM_C2);
        float den = (mu1sq + mu2sq + SSIM_C1) * (s11 + s22 + SSIM_C2);
        acc += num / den;

        // shift ring, load plane d+6
#pragma unroll
        for (int k = 0; k < 10; k++) {
            r1[k] = r1[k + 1];
            r2[k] = r2[k + 1];
            r11[k] = r11[k + 1];
            r22[k] = r22[k + 1];
            r12[k] = r12[k + 1];
        }
        int nd = d + 6;
        bool ok = nd < D_;
        long long o = (long long)nd * HW_;
        r1[10] = ok ? t0[o] : 0.f;
        r2[10] = ok ? t1[o] : 0.f;
        r11[10] = ok ? t2[o] : 0.f;
        r22[10] = ok ? t3[o] : 0.f;
        r12[10] = ok ? t4[o] : 0.f;
    }

    // Block reduction: 5 warps of 32
    __shared__ float red[5];
#pragma unroll
    for (int o = 16; o > 0; o >>= 1)
        acc += __shfl_down_sync(0xffffffffu, acc, o);
    if ((threadIdx.x & 31) == 0) red[threadIdx.x >> 5] = acc;
    __syncthreads();
    if (threadIdx.x == 0) {
        float s = red[0] + red[1] + red[2] + red[3] + red[4];
        atomicAdd(&g_acc[c], s);
    }
}

__global__ void zero_kernel() {
    if (threadIdx.x < C_) g_acc[threadIdx.x] = 0.f;
}

__global__ void final_kernel(float* __restrict__ out) {
    int c = threadIdx.x;
    if (c < C_) out[c] = 1.f - g_acc[c] * (1.f / (float)NVOX_PER_CH);
}

extern "C" void kernel_launch(void* const* d_in, const int* in_sizes, int n_in,
                              void* d_out, int out_size) {
    (void)in_sizes; (void)n_in; (void)out_size;
    const float* img1 = (const float*)d_in[0];
    const float* img2 = (const float*)d_in[1];
    float* out = (float*)d_out;

    zero_kernel<<<1, 32>>>();
    dim3 gA(W_ / TS, H_ / TS, NSLICE);  // (5, 5, 512)
    passA_kernel<<<gA, 256>>>(img1, img2);
    passB_kernel<<<B_ * C_ * H_, 160>>>();
    final_kernel<<<1, 32>>>(out);
}

// round 4
// speedup vs baseline: 1.1883x; 1.1883x over previous
#include <cuda_runtime.h>
#include <cstdint>

// Problem dims
#define B_  2
#define C_  4
#define D_  64
#define H_  160
#define W_  160
#define HW_ (H_ * W_)            // 25600
#define BC_ (B_ * C_)            // 8
#define NSLICE (BC_ * D_)        // 512
#define NVOX_PER_CH (B_ * D_ * H_ * W_)  // 3,276,800

// D-padded scratch: planes 0..79, real data at [5, 69), rest stays zero (.bss).
#define DP_ 80
#define PLANE_OFF 5

// Gaussian window (k=11, sigma=1.5), normalized, symmetric. Literals so ptxas
// uses FFMA-imm (rt=1).
#define GW0 0.00102838f
#define GW1 0.00759876f
#define GW2 0.03600077f
#define GW3 0.10936069f
#define GW4 0.21300554f
#define GW5 0.26601173f

#define SSIM_C1 1.0e-4f
#define SSIM_C2 9.0e-4f

__host__ __device__ constexpr float gw(int t) {
    return t == 0 ? GW0 : t == 1 ? GW1 : t == 2 ? GW2 : t == 3 ? GW3 :
           t == 4 ? GW4 : t == 5 ? GW5 : t == 6 ? GW4 : t == 7 ? GW3 :
           t == 8 ? GW2 : t == 9 ? GW1 : GW0;
}

// Scratch: 5 fields x [BC, DP, H, W] fp32 = 327.7 MB static (zero-initialized)
#define FS2 ((long long)BC_ * DP_ * HW_)  // 16,384,000
__device__ float g_tmp[5LL * FS2];
__device__ float g_acc[C_];

// 11-tap symmetric conv over v[J..J+10], constant indices.
template <int J>
__device__ __forceinline__ float conv11(const float (&v)[14]) {
    float s = v[J + 0] * GW0;
    s = fmaf(v[J + 1], GW1, s);
    s = fmaf(v[J + 2], GW2, s);
    s = fmaf(v[J + 3], GW3, s);
    s = fmaf(v[J + 4], GW4, s);
    s = fmaf(v[J + 5], GW5, s);
    s = fmaf(v[J + 6], GW4, s);
    s = fmaf(v[J + 7], GW3, s);
    s = fmaf(v[J + 8], GW2, s);
    s = fmaf(v[J + 9], GW1, s);
    s = fmaf(v[J + 10], GW0, s);
    return s;
}

// ---------------------------------------------------------------------------
// Pass A: per D-slice, separable W-then-H conv of the 5 fields
//   fields: x1, x2, x1*x1, x2*x2, x1*x2
// Tile: 32x32 outputs, halo 5 -> 42x42 input tile in smem.
// ---------------------------------------------------------------------------
#define TS 32
#define HALO 5
#define TIN 42  // TS + 2*HALO

__global__ void __launch_bounds__(256) passA_kernel(
    const float* __restrict__ img1, const float* __restrict__ img2) {
    __shared__ float s1[TIN][TIN + 1];        // stride 43: conflict-free
    __shared__ float s2[TIN][TIN + 1];
    __shared__ float mid[5][TIN][TS + 1];     // stride 33: conflict-free

    const int slice = blockIdx.z;             // bc*D + d
    const int ty0 = blockIdx.y * TS;
    const int tx0 = blockIdx.x * TS;
    const int tid = threadIdx.x;

    const float* p1 = img1 + (long long)slice * HW_;
    const float* p2 = img2 + (long long)slice * HW_;

    // Load 42x42 halo tiles (zero padding outside image)
    for (int i = tid; i < TIN * TIN; i += 256) {
        int y = i / TIN, x = i - y * TIN;
        int gy = ty0 + y - HALO;
        int gx = tx0 + x - HALO;
        bool ok = ((unsigned)gy < (unsigned)H_) && ((unsigned)gx < (unsigned)W_);
        float a = 0.f, b = 0.f;
        if (ok) {
            int gi = gy * W_ + gx;
            a = p1[gi];
            b = p2[gi];
        }
        s1[y][x] = a;
        s2[y][x] = b;
    }
    __syncthreads();

    // W-direction conv: 42 rows x 32 cols of mid, each thread does 4 consecutive x
    for (int i = tid; i < TIN * 8; i += 256) {
        int y = i >> 3;
        int x0 = (i & 7) << 2;
        float v1[14], v2[14], q11[14], q22[14], q12[14];
#pragma unroll
        for (int t = 0; t < 14; t++) {
            float a = s1[y][x0 + t];
            float b = s2[y][x0 + t];
            v1[t] = a;
            v2[t] = b;
            q11[t] = a * a;
            q22[t] = b * b;
            q12[t] = a * b;
        }
#define STORE4(F, ARR)                               \
        mid[F][y][x0 + 0] = conv11<0>(ARR);          \
        mid[F][y][x0 + 1] = conv11<1>(ARR);          \
        mid[F][y][x0 + 2] = conv11<2>(ARR);          \
        mid[F][y][x0 + 3] = conv11<3>(ARR);
        STORE4(0, v1)
        STORE4(1, v2)
        STORE4(2, q11)
        STORE4(3, q22)
        STORE4(4, q12)
#undef STORE4
    }
    __syncthreads();

    // H-direction conv: 32x32 outputs, each thread does 4 consecutive y at one x
    {
        int x = tid & 31;
        int y0 = (tid >> 5) << 2;  // 0..28 step 4
        const int bc = slice / D_;
        const int d = slice - bc * D_;
        long long obase = (long long)bc * (DP_ * (long long)HW_) +
                          (long long)(d + PLANE_OFF) * HW_ +
                          (long long)(ty0 + y0) * W_ + (tx0 + x);
#pragma unroll
        for (int f = 0; f < 5; f++) {
            float v[14];
#pragma unroll
            for (int t = 0; t < 14; t++) v[t] = mid[f][y0 + t][x];
            float* op = g_tmp + (long long)f * FS2 + obase;
            op[0 * W_] = conv11<0>(v);
            op[1 * W_] = conv11<1>(v);
            op[2 * W_] = conv11<2>(v);
            op[3 * W_] = conv11<3>(v);
        }
    }
}

// ---------------------------------------------------------------------------
// Pass B: D-direction conv via rotating register ring WITHOUT shifts:
// unroll-by-11 so the ring slot for each tap is a compile-time constant.
// Slot s holds padded plane q with q % 11 == s. At output d (u = d % 11),
// tap t lives in slot (u + t) % 11. After the output, plane d+11 overwrites
// slot u. Zero-padding in D removes all boundary predicates.
// ---------------------------------------------------------------------------
template <int U>
__device__ __forceinline__ float convU(const float (&r)[11]) {
    float s = r[U] * gw(0);
#pragma unroll
    for (int k = 1; k < 11; k++) {
        s = fmaf(r[(U + k) % 11], gw(k), s);
    }
    return s;
}

template <int U>
__device__ __forceinline__ void stepU(
    float (&r1)[11], float (&r2)[11], float (&r11)[11],
    float (&r22)[11], float (&r12)[11],
    const float* __restrict__ t0, const float* __restrict__ t1,
    const float* __restrict__ t2, const float* __restrict__ t3,
    const float* __restrict__ t4,
    long long o, float& acc) {
    float mu1 = convU<U>(r1);
    float mu2 = convU<U>(r2);
    float e11 = convU<U>(r11);
    float e22 = convU<U>(r22);
    float e12 = convU<U>(r12);

    float mu1sq = mu1 * mu1;
    float mu2sq = mu2 * mu2;
    float mu12 = mu1 * mu2;
    float s11 = e11 - mu1sq;
    float s22 = e22 - mu2sq;
    float s12 = e12 - mu12;

    float num = (2.f * mu12 + SSIM_C1) * (2.f * s12 + SSIM_C2);
    float den = (mu1sq + mu2sq + SSIM_C1) * (s11 + s22 + SSIM_C2);
    acc += __fdividef(num, den);

    // refill slot U with padded plane d+11 (always in-bounds: pads are zero)
    r1[U] = t0[o];
    r2[U] = t1[o];
    r11[U] = t2[o];
    r22[U] = t3[o];
    r12[U] = t4[o];
}

__global__ void __launch_bounds__(160) passB_kernel() {
    const int bid = blockIdx.x;          // (b*C + c)*H + y
    const int y = bid % H_;
    const int bc = bid / H_;             // b*C + c
    const int c = bc % C_;
    const int x = threadIdx.x;           // 0..159

    const long long colbase = (long long)bc * (DP_ * (long long)HW_) +
                              (long long)y * W_ + x;
    const float* t0 = g_tmp + 0LL * FS2 + colbase;
    const float* t1 = g_tmp + 1LL * FS2 + colbase;
    const float* t2 = g_tmp + 2LL * FS2 + colbase;
    const float* t3 = g_tmp + 3LL * FS2 + colbase;
    const float* t4 = g_tmp + 4LL * FS2 + colbase;

    float r1[11], r2[11], r11[11], r22[11], r12[11];
    // Preload padded planes 0..10 into slots 0..10 (slot = plane % 11).
#pragma unroll
    for (int k = 0; k < 11; k++) {
        long long o = (long long)k * HW_;
        r1[k] = t0[o];
        r2[k] = t1[o];
        r11[k] = t2[o];
        r22[k] = t3[o];
        r12[k] = t4[o];
    }

    float acc = 0.f;
    long long o = 11LL * HW_;  // next plane to load

#define STEP(U) stepU<U>(r1, r2, r11, r22, r12, t0, t1, t2, t3, t4, o, acc); o += HW_;

    // d = 0..54 : five full rotations of 11
#pragma unroll 1
    for (int blk = 0; blk < 5; blk++) {
        STEP(0) STEP(1) STEP(2) STEP(3) STEP(4) STEP(5)
        STEP(6) STEP(7) STEP(8) STEP(9) STEP(10)
    }
    // d = 55..63 : tail (loads reach padded plane 74 < 80, all zero pads)
    STEP(0) STEP(1) STEP(2) STEP(3) STEP(4) STEP(5) STEP(6) STEP(7) STEP(8)
#undef STEP

    // Block reduction: 5 warps of 32
    __shared__ float red[5];
#pragma unroll
    for (int off = 16; off > 0; off >>= 1)
        acc += __shfl_down_sync(0xffffffffu, acc, off);
    if ((threadIdx.x & 31) == 0) red[threadIdx.x >> 5] = acc;
    __syncthreads();
    if (threadIdx.x == 0) {
        float s = red[0] + red[1] + red[2] + red[3] + red[4];
        atomicAdd(&g_acc[c], s);
    }
}

// Reads the per-channel sums, writes the loss, and re-zeroes g_acc so the
// next call (graph replay) starts clean. First call relies on .bss zero-init.
__global__ void final_kernel(float* __restrict__ out) {
    int c = threadIdx.x;
    if (c < C_) {
        out[c] = 1.f - g_acc[c] * (1.f / (float)NVOX_PER_CH);
        g_acc[c] = 0.f;
    }
}

extern "C" void kernel_launch(void* const* d_in, const int* in_sizes, int n_in,
                              void* d_out, int out_size) {
    (void)in_sizes; (void)n_in; (void)out_size;
    const float* img1 = (const float*)d_in[0];
    const float* img2 = (const float*)d_in[1];
    float* out = (float*)d_out;

    dim3 gA(W_ / TS, H_ / TS, NSLICE);  // (5, 5, 512)
    passA_kernel<<<gA, 256>>>(img1, img2);
    passB_kernel<<<BC_ * H_, 160>>>();
    final_kernel<<<1, 32>>>(out);
}

// round 5
// speedup vs baseline: 1.2933x; 1.0884x over previous
#include <cuda_runtime.h>
#include <cstdint>

// Problem dims
#define B_  2
#define C_  4
#define D_  64
#define H_  160
#define W_  160
#define HW_ (H_ * W_)            // 25600
#define BC_ (B_ * C_)            // 8
#define NSLICE (BC_ * D_)        // 512
#define NVOX_PER_CH (B_ * D_ * H_ * W_)  // 3,276,800

// Gaussian window (k=11, sigma=1.5), normalized, symmetric. Literals so ptxas
// uses FFMA-imm (rt=1).
#define GW0 0.00102838f
#define GW1 0.00759876f
#define GW2 0.03600077f
#define GW3 0.10936069f
#define GW4 0.21300554f
#define GW5 0.26601173f

#define SSIM_C1 1.0e-4f
#define SSIM_C2 9.0e-4f

__host__ __device__ constexpr float gw(int t) {
    return t == 0 ? GW0 : t == 1 ? GW1 : t == 2 ? GW2 : t == 3 ? GW3 :
           t == 4 ? GW4 : t == 5 ? GW5 : t == 6 ? GW4 : t == 7 ? GW3 :
           t == 8 ? GW2 : t == 9 ? GW1 : GW0;
}

// Scratch (AoS): g4 = (mu1,mu2,e11,e22) per voxel, g1 = e12 per voxel.
// [NSLICE][HW] layout, no pad planes. 210MB + 52MB static.
__device__ float4 g4[(long long)NSLICE * HW_];
__device__ float  g1[(long long)NSLICE * HW_];
__device__ float  g_acc[C_];

// 11-tap symmetric conv over v[J..J+10] of a 14-float register array.
template <int J>
__device__ __forceinline__ float conv11(const float (&v)[14]) {
    float s = v[J] * GW0;
#pragma unroll
    for (int k = 1; k < 11; k++) s = fmaf(v[J + k], gw(k), s);
    return s;
}

// Same over a 20-float register array with start S (S in 3..6).
template <int S>
__device__ __forceinline__ float conv20(const float (&v)[20]) {
    float s = v[S] * GW0;
#pragma unroll
    for (int k = 1; k < 11; k++) s = fmaf(v[S + k], gw(k), s);
    return s;
}

// ---------------------------------------------------------------------------
// Pass A: per D-slice, separable W-then-H conv of the 5 fields
//   fields: x1, x2, x1*x1, x2*x2, x1*x2
// Tile: 32x32 outputs. s tiles: 42 rows x 48 cols (col j <-> gx = tx0-8+j),
// fully float4-tiled for vector global loads + vector smem ops.
// ---------------------------------------------------------------------------
#define TS 32
#define HALO 5
#define TIN 42   // TS + 2*HALO rows
#define SNX 48   // padded/loaded cols (j = 0..47), 16B-aligned rows
#define MNX 36   // mid row pad (16B-aligned)

__global__ void __launch_bounds__(256) passA_kernel(
    const float* __restrict__ img1, const float* __restrict__ img2) {
    __shared__ float s1[TIN][SNX];      // 8.06 KB
    __shared__ float s2[TIN][SNX];      // 8.06 KB
    __shared__ float mid[5][TIN][MNX];  // 30.2 KB   (total 46.4 KB)

    const int slice = blockIdx.z;             // bc*D + d
    const int ty0 = blockIdx.y * TS;
    const int tx0 = blockIdx.x * TS;
    const int tid = threadIdx.x;

    const float4* p1 = (const float4*)(img1 + (long long)slice * HW_);
    const float4* p2 = (const float4*)(img2 + (long long)slice * HW_);

    // Phase 1: vector halo load. Item i -> (row y, float4-chunk k), 42x12 items.
    // gx0 = tx0 - 8 + 4k is 4-aligned; per-float4 OOB predication is exact.
    for (int i = tid; i < TIN * 12; i += 256) {
        int y = i / 12, k = i - y * 12;
        int gy = ty0 + y - HALO;
        int gx0 = tx0 - 8 + 4 * k;
        float4 a = make_float4(0.f, 0.f, 0.f, 0.f);
        float4 b = a;
        if (((unsigned)gy < (unsigned)H_) && ((unsigned)gx0 < (unsigned)W_)) {
            int gi = (gy * W_ + gx0) >> 2;
            a = p1[gi];
            b = p2[gi];
        }
        *(float4*)&s1[y][4 * k] = a;
        *(float4*)&s2[y][4 * k] = b;
    }
    __syncthreads();

    // Phase 2: W-conv. 42 rows x 8 x-quads = 336 items.
    // Quad x0 needs window j = x0+3 .. x0+16 -> load j = x0 .. x0+19 via 5 LDS.128.
    for (int i = tid; i < TIN * 8; i += 256) {
        int y = i >> 3;
        int x0 = (i & 7) << 2;
        float A[20], Bv[20];
#pragma unroll
        for (int k = 0; k < 5; k++) {
            *(float4*)&A[4 * k]  = *(const float4*)&s1[y][x0 + 4 * k];
            *(float4*)&Bv[4 * k] = *(const float4*)&s2[y][x0 + 4 * k];
        }
        float4 r;
        // field 0: mu1-partial
        r.x = conv20<3>(A); r.y = conv20<4>(A); r.z = conv20<5>(A); r.w = conv20<6>(A);
        *(float4*)&mid[0][y][x0] = r;
        // field 1: mu2-partial
        r.x = conv20<3>(Bv); r.y = conv20<4>(Bv); r.z = conv20<5>(Bv); r.w = conv20<6>(Bv);
        *(float4*)&mid[1][y][x0] = r;
        // field 2: E[x1^2]-partial
        {
            float sq[14];
#pragma unroll
            for (int t = 0; t < 14; t++) sq[t] = A[t + 3] * A[t + 3];
            r.x = conv11<0>(sq); r.y = conv11<1>(sq); r.z = conv11<2>(sq); r.w = conv11<3>(sq);
            *(float4*)&mid[2][y][x0] = r;
        }
        // field 3: E[x2^2]-partial
        {
            float sq[14];
#pragma unroll
            for (int t = 0; t < 14; t++) sq[t] = Bv[t + 3] * Bv[t + 3];
            r.x = conv11<0>(sq); r.y = conv11<1>(sq); r.z = conv11<2>(sq); r.w = conv11<3>(sq);
            *(float4*)&mid[3][y][x0] = r;
        }
        // field 4: E[x1*x2]-partial
        {
            float sq[14];
#pragma unroll
            for (int t = 0; t < 14; t++) sq[t] = A[t + 3] * Bv[t + 3];
            r.x = conv11<0>(sq); r.y = conv11<1>(sq); r.z = conv11<2>(sq); r.w = conv11<3>(sq);
            *(float4*)&mid[4][y][x0] = r;
        }
    }
    __syncthreads();

    // Phase 3: H-conv, y-sliding (bytes-optimal scalar LDS), AoS stores.
    // Thread -> (x = tid&31, y0 = (tid>>5)*4): 4 outputs at consecutive y.
    {
        int x = tid & 31;
        int y0 = (tid >> 5) << 2;
        float m1[4], m2[4], E11[4], E22[4], E12[4];
        float v[14];
#define HCONV(DST)                                                     \
        DST[0] = conv11<0>(v); DST[1] = conv11<1>(v);                  \
        DST[2] = conv11<2>(v); DST[3] = conv11<3>(v);
#pragma unroll
        for (int t = 0; t < 14; t++) v[t] = mid[0][y0 + t][x];
        HCONV(m1)
#pragma unroll
        for (int t = 0; t < 14; t++) v[t] = mid[1][y0 + t][x];
        HCONV(m2)
#pragma unroll
        for (int t = 0; t < 14; t++) v[t] = mid[2][y0 + t][x];
        HCONV(E11)
#pragma unroll
        for (int t = 0; t < 14; t++) v[t] = mid[3][y0 + t][x];
        HCONV(E22)
#pragma unroll
        for (int t = 0; t < 14; t++) v[t] = mid[4][y0 + t][x];
        HCONV(E12)
#undef HCONV
        long long vox = (long long)slice * HW_ + (long long)(ty0 + y0) * W_ + (tx0 + x);
#pragma unroll
        for (int u = 0; u < 4; u++) {
            g4[vox + u * W_] = make_float4(m1[u], m2[u], E11[u], E22[u]);
            g1[vox + u * W_] = E12[u];
        }
    }
}

// ---------------------------------------------------------------------------
// Pass B: D-conv via rotating register ring (unroll-by-11, compile-time slots)
// fused with SSIM map + per-channel reduction. Boundary handling via
// compile-time predicated loads (no physical pad planes).
// Slot s holds "padded plane" p (= real d+5) with p % 11 == s.
// ---------------------------------------------------------------------------
template <int U>
__device__ __forceinline__ float convU(const float (&r)[11]) {
    float s = r[U] * gw(0);
#pragma unroll
    for (int k = 1; k < 11; k++) s = fmaf(r[(U + k) % 11], gw(k), s);
    return s;
}

template <int U, bool LOAD>
__device__ __forceinline__ void stepU(
    float (&a)[11], float (&b)[11], float (&c11)[11],
    float (&c22)[11], float (&c12)[11],
    const float4* __restrict__ t4, const float* __restrict__ t1,
    long long o, float& acc) {
    float mu1 = convU<U>(a);
    float mu2 = convU<U>(b);
    float e11 = convU<U>(c11);
    float e22 = convU<U>(c22);
    float e12 = convU<U>(c12);

    float mu1sq = mu1 * mu1;
    float mu2sq = mu2 * mu2;
    float mu12 = mu1 * mu2;
    float s11 = e11 - mu1sq;
    float s22 = e22 - mu2sq;
    float s12 = e12 - mu12;

    float num = (2.f * mu12 + SSIM_C1) * (2.f * s12 + SSIM_C2);
    float den = (mu1sq + mu2sq + SSIM_C1) * (s11 + s22 + SSIM_C2);
    acc += __fdividef(num, den);

    if (LOAD) {
        float4 v = t4[o];
        a[U] = v.x; b[U] = v.y; c11[U] = v.z; c22[U] = v.w;
        c12[U] = t1[o];
    } else {
        a[U] = 0.f; b[U] = 0.f; c11[U] = 0.f; c22[U] = 0.f; c12[U] = 0.f;
    }
}

__global__ void __launch_bounds__(160) passB_kernel() {
    const int bid = blockIdx.x;          // (b*C + c)*H + y
    const int y = bid % H_;
    const int bc = bid / H_;             // b*C + c
    const int c = bc % C_;
    const int x = threadIdx.x;           // 0..159

    const long long colbase = (long long)bc * D_ * HW_ + (long long)y * W_ + x;
    const float4* t4 = g4 + colbase;
    const float*  t1 = g1 + colbase;

    float a[11], b[11], c11[11], c22[11], c12[11];
    // Preload slots k = 0..10 <- padded plane k (real d = k-5); zero if OOB.
#pragma unroll
    for (int k = 0; k < 11; k++) {
        if (k >= 5) {
            long long o = (long long)(k - 5) * HW_;
            float4 v = t4[o];
            a[k] = v.x; b[k] = v.y; c11[k] = v.z; c22[k] = v.w;
            c12[k] = t1[o];
        } else {
            a[k] = 0.f; b[k] = 0.f; c11[k] = 0.f; c22[k] = 0.f; c12[k] = 0.f;
        }
    }

    float acc = 0.f;
    long long o = 6LL * HW_;  // output d refills real plane d+6

#define STEP(U, L) stepU<U, L>(a, b, c11, c22, c12, t4, t1, o, acc); o += HW_;

    // d = 0..54 : five full rotations (loads real planes 6..60, always valid)
#pragma unroll 1
    for (int blk = 0; blk < 5; blk++) {
        STEP(0, true) STEP(1, true) STEP(2, true) STEP(3, true)
        STEP(4, true) STEP(5, true) STEP(6, true) STEP(7, true)
        STEP(8, true) STEP(9, true) STEP(10, true)
    }
    // d = 55..63 : tail; load valid only while d+6 <= 63 (d <= 57)
    STEP(0, true) STEP(1, true) STEP(2, true)
    STEP(3, false) STEP(4, false) STEP(5, false)
    STEP(6, false) STEP(7, false) STEP(8, false)
#undef STEP

    // Block reduction: 5 warps of 32
    __shared__ float red[5];
#pragma unroll
    for (int off = 16; off > 0; off >>= 1)
        acc += __shfl_down_sync(0xffffffffu, acc, off);
    if ((threadIdx.x & 31) == 0) red[threadIdx.x >> 5] = acc;
    __syncthreads();
    if (threadIdx.x == 0) {
        float s = red[0] + red[1] + red[2] + red[3] + red[4];
        atomicAdd(&g_acc[c], s);
    }
}

// Reads the per-channel sums, writes the loss, and re-zeroes g_acc so the
// next call (graph replay) starts clean. First call relies on .bss zero-init.
__global__ void final_kernel(float* __restrict__ out) {
    int c = threadIdx.x;
    if (c < C_) {
        out[c] = 1.f - g_acc[c] * (1.f / (float)NVOX_PER_CH);
        g_acc[c] = 0.f;
    }
}

extern "C" void kernel_launch(void* const* d_in, const int* in_sizes, int n_in,
                              void* d_out, int out_size) {
    (void)in_sizes; (void)n_in; (void)out_size;
    const float* img1 = (const float*)d_in[0];
    const float* img2 = (const float*)d_in[1];
    float* out = (float*)d_out;

    dim3 gA(W_ / TS, H_ / TS, NSLICE);  // (5, 5, 512)
    passA_kernel<<<gA, 256>>>(img1, img2);
    passB_kernel<<<BC_ * H_, 160>>>();
    final_kernel<<<1, 32>>>(out);
}

// round 6
// speedup vs baseline: 1.3385x; 1.0350x over previous
#include <cuda_runtime.h>
#include <cstdint>

// Problem dims
#define B_  2
#define C_  4
#define D_  64
#define H_  160
#define W_  160
#define HW_ (H_ * W_)            // 25600
#define BC_ (B_ * C_)            // 8
#define NSLICE (BC_ * D_)        // 512
#define NVOX_PER_CH (B_ * D_ * H_ * W_)  // 3,276,800

// Gaussian window (k=11, sigma=1.5), normalized, symmetric. Literals so ptxas
// uses FFMA-imm (rt=1).
#define GW0 0.00102838f
#define GW1 0.00759876f
#define GW2 0.03600077f
#define GW3 0.10936069f
#define GW4 0.21300554f
#define GW5 0.26601173f

#define SSIM_C1 1.0e-4f
#define SSIM_C2 9.0e-4f

__host__ __device__ constexpr float gw(int t) {
    return t == 0 ? GW0 : t == 1 ? GW1 : t == 2 ? GW2 : t == 3 ? GW3 :
           t == 4 ? GW4 : t == 5 ? GW5 : t == 6 ? GW4 : t == 7 ? GW3 :
           t == 8 ? GW2 : t == 9 ? GW1 : GW0;
}

// Scratch (AoS): g4 = (mu1,mu2,e11,e22) per voxel, g1 = e12 per voxel.
// [NSLICE][HW] layout, no pad planes. 210MB + 52MB static.
__device__ float4 g4[(long long)NSLICE * HW_];
__device__ float  g1[(long long)NSLICE * HW_];
__device__ float  g_acc[C_];

// 11-tap symmetric conv over v[J..J+10] of a 14-float register array.
template <int J>
__device__ __forceinline__ float conv11(const float (&v)[14]) {
    float s = v[J] * GW0;
#pragma unroll
    for (int k = 1; k < 11; k++) s = fmaf(v[J + k], gw(k), s);
    return s;
}

// Same over a 20-float register array with start S (S in 3..6).
template <int S>
__device__ __forceinline__ float conv20(const float (&v)[20]) {
    float s = v[S] * GW0;
#pragma unroll
    for (int k = 1; k < 11; k++) s = fmaf(v[S + k], gw(k), s);
    return s;
}

// ---------------------------------------------------------------------------
// Pass A: per D-slice, separable W-then-H conv of the 5 fields
//   fields: x1, x2, x1*x1, x2*x2, x1*x2
// Tile: 32x32 outputs. s tiles: 42 rows x 48 cols (col j <-> gx = tx0-8+j),
// fully float4-tiled for vector global loads + vector smem ops.
// ---------------------------------------------------------------------------
#define TS 32
#define HALO 5
#define TIN 42   // TS + 2*HALO rows
#define SNX 48   // padded/loaded cols (j = 0..47), 16B-aligned rows
#define MNX 36   // mid row pad (16B-aligned)

__global__ void __launch_bounds__(256) passA_kernel(
    const float* __restrict__ img1, const float* __restrict__ img2) {
    __shared__ float s1[TIN][SNX];      // 8.06 KB
    __shared__ float s2[TIN][SNX];      // 8.06 KB
    __shared__ float mid[5][TIN][MNX];  // 30.2 KB   (total 46.4 KB)

    const int slice = blockIdx.z;             // bc*D + d
    const int ty0 = blockIdx.y * TS;
    const int tx0 = blockIdx.x * TS;
    const int tid = threadIdx.x;

    const float4* p1 = (const float4*)(img1 + (long long)slice * HW_);
    const float4* p2 = (const float4*)(img2 + (long long)slice * HW_);

    // Phase 1: vector halo load. Item i -> (row y, float4-chunk k), 42x12 items.
    // gx0 = tx0 - 8 + 4k is 4-aligned; per-float4 OOB predication is exact.
    for (int i = tid; i < TIN * 12; i += 256) {
        int y = i / 12, k = i - y * 12;
        int gy = ty0 + y - HALO;
        int gx0 = tx0 - 8 + 4 * k;
        float4 a = make_float4(0.f, 0.f, 0.f, 0.f);
        float4 b = a;
        if (((unsigned)gy < (unsigned)H_) && ((unsigned)gx0 < (unsigned)W_)) {
            int gi = (gy * W_ + gx0) >> 2;
            a = p1[gi];
            b = p2[gi];
        }
        *(float4*)&s1[y][4 * k] = a;
        *(float4*)&s2[y][4 * k] = b;
    }
    __syncthreads();

    // Phase 2: W-conv. 42 rows x 8 x-quads = 336 items.
    // Quad x0 needs window j = x0+3 .. x0+16 -> load j = x0 .. x0+19 via 5 LDS.128.
    for (int i = tid; i < TIN * 8; i += 256) {
        int y = i >> 3;
        int x0 = (i & 7) << 2;
        float A[20], Bv[20];
#pragma unroll
        for (int k = 0; k < 5; k++) {
            *(float4*)&A[4 * k]  = *(const float4*)&s1[y][x0 + 4 * k];
            *(float4*)&Bv[4 * k] = *(const float4*)&s2[y][x0 + 4 * k];
        }
        float4 r;
        // field 0: mu1-partial
        r.x = conv20<3>(A); r.y = conv20<4>(A); r.z = conv20<5>(A); r.w = conv20<6>(A);
        *(float4*)&mid[0][y][x0] = r;
        // field 1: mu2-partial
        r.x = conv20<3>(Bv); r.y = conv20<4>(Bv); r.z = conv20<5>(Bv); r.w = conv20<6>(Bv);
        *(float4*)&mid[1][y][x0] = r;
        // field 2: E[x1^2]-partial
        {
            float sq[14];
#pragma unroll
            for (int t = 0; t < 14; t++) sq[t] = A[t + 3] * A[t + 3];
            r.x = conv11<0>(sq); r.y = conv11<1>(sq); r.z = conv11<2>(sq); r.w = conv11<3>(sq);
            *(float4*)&mid[2][y][x0] = r;
        }
        // field 3: E[x2^2]-partial
        {
            float sq[14];
#pragma unroll
            for (int t = 0; t < 14; t++) sq[t] = Bv[t + 3] * Bv[t + 3];
            r.x = conv11<0>(sq); r.y = conv11<1>(sq); r.z = conv11<2>(sq); r.w = conv11<3>(sq);
            *(float4*)&mid[3][y][x0] = r;
        }
        // field 4: E[x1*x2]-partial
        {
            float sq[14];
#pragma unroll
            for (int t = 0; t < 14; t++) sq[t] = A[t + 3] * Bv[t + 3];
            r.x = conv11<0>(sq); r.y = conv11<1>(sq); r.z = conv11<2>(sq); r.w = conv11<3>(sq);
            *(float4*)&mid[4][y][x0] = r;
        }
    }
    __syncthreads();

    // Phase 3: H-conv, y-sliding (bytes-optimal scalar LDS), AoS stores.
    // Thread -> (x = tid&31, y0 = (tid>>5)*4): 4 outputs at consecutive y.
    {
        int x = tid & 31;
        int y0 = (tid >> 5) << 2;
        float m1[4], m2[4], E11[4], E22[4], E12[4];
        float v[14];
#define HCONV(DST)                                                     \
        DST[0] = conv11<0>(v); DST[1] = conv11<1>(v);                  \
        DST[2] = conv11<2>(v); DST[3] = conv11<3>(v);
#pragma unroll
        for (int t = 0; t < 14; t++) v[t] = mid[0][y0 + t][x];
        HCONV(m1)
#pragma unroll
        for (int t = 0; t < 14; t++) v[t] = mid[1][y0 + t][x];
        HCONV(m2)
#pragma unroll
        for (int t = 0; t < 14; t++) v[t] = mid[2][y0 + t][x];
        HCONV(E11)
#pragma unroll
        for (int t = 0; t < 14; t++) v[t] = mid[3][y0 + t][x];
        HCONV(E22)
#pragma unroll
        for (int t = 0; t < 14; t++) v[t] = mid[4][y0 + t][x];
        HCONV(E12)
#undef HCONV
        long long vox = (long long)slice * HW_ + (long long)(ty0 + y0) * W_ + (tx0 + x);
#pragma unroll
        for (int u = 0; u < 4; u++) {
            g4[vox + u * W_] = make_float4(m1[u], m2[u], E11[u], E22[u]);
            g1[vox + u * W_] = E12[u];
        }
    }
}

// ---------------------------------------------------------------------------
// Pass B: D-conv via 13-deep rotating register ring. Slot = plane % 13.
// At output step d, taps are planes d-5..d+5 (slots (d+8+k)%13, k=0..10),
// and the refill loads plane d+8 into slot (d+8)%13 — first consumed at
// step d+3, giving ~3 steps (~800+ wall cycles) of load slack to cover
// DRAM/L2 latency. All slot indices are compile-time (d%13 templated).
// ---------------------------------------------------------------------------
template <int J>
__device__ __forceinline__ float conv13(const float (&r)[13]) {
    float s = r[(J + 8) % 13] * gw(0);
#pragma unroll
    for (int k = 1; k < 11; k++) s = fmaf(r[(J + 8 + k) % 13], gw(k), s);
    return s;
}

template <int J, bool LOAD>
__device__ __forceinline__ void stepJ(
    float (&a)[13], float (&b)[13], float (&c11)[13],
    float (&c22)[13], float (&c12)[13],
    const float4* __restrict__ t4, const float* __restrict__ t1,
    long long o, float& acc) {
    float mu1 = conv13<J>(a);
    float mu2 = conv13<J>(b);
    float e11 = conv13<J>(c11);
    float e22 = conv13<J>(c22);
    float e12 = conv13<J>(c12);

    float mu1sq = mu1 * mu1;
    float mu2sq = mu2 * mu2;
    float mu12 = mu1 * mu2;
    float s11 = e11 - mu1sq;
    float s22 = e22 - mu2sq;
    float s12 = e12 - mu12;

    float num = (2.f * mu12 + SSIM_C1) * (2.f * s12 + SSIM_C2);
    float den = (mu1sq + mu2sq + SSIM_C1) * (s11 + s22 + SSIM_C2);
    acc += __fdividef(num, den);

    // Refill slot (J+8)%13 with plane d+8 (same slot as tap 0, already read).
    constexpr int RS = (J + 8) % 13;
    if (LOAD) {
        float4 v = t4[o];
        a[RS] = v.x; b[RS] = v.y; c11[RS] = v.z; c22[RS] = v.w;
        c12[RS] = t1[o];
    } else {
        a[RS] = 0.f; b[RS] = 0.f; c11[RS] = 0.f; c22[RS] = 0.f; c12[RS] = 0.f;
    }
}

__global__ void __launch_bounds__(160) passB_kernel() {
    const int bid = blockIdx.x;          // (b*C + c)*H + y
    const int y = bid % H_;
    const int bc = bid / H_;             // b*C + c
    const int c = bc % C_;
    const int x = threadIdx.x;           // 0..159

    const long long colbase = (long long)bc * D_ * HW_ + (long long)y * W_ + x;
    const float4* t4 = g4 + colbase;
    const float*  t1 = g1 + colbase;

    float a[13], b[13], c11[13], c22[13], c12[13];
    // Preload: slots 0..7 <- planes 0..7; slots 8..12 <- 0 (planes -5..-1).
#pragma unroll
    for (int k = 0; k < 8; k++) {
        long long o = (long long)k * HW_;
        float4 v = t4[o];
        a[k] = v.x; b[k] = v.y; c11[k] = v.z; c22[k] = v.w;
        c12[k] = t1[o];
    }
#pragma unroll
    for (int k = 8; k < 13; k++) {
        a[k] = 0.f; b[k] = 0.f; c11[k] = 0.f; c22[k] = 0.f; c12[k] = 0.f;
    }

    float acc = 0.f;
    long long o = 8LL * HW_;  // step d refills plane d+8

#define STEP(J, L) stepJ<J, L>(a, b, c11, c22, c12, t4, t1, o, acc); o += HW_;

    // d = 0..51 : four full rotations of 13 (refills planes 8..59, all valid)
#pragma unroll 1
    for (int r = 0; r < 4; r++) {
        STEP(0, true)  STEP(1, true)  STEP(2, true)  STEP(3, true)
        STEP(4, true)  STEP(5, true)  STEP(6, true)  STEP(7, true)
        STEP(8, true)  STEP(9, true)  STEP(10, true) STEP(11, true)
        STEP(12, true)
    }
    // d = 52..63 : refill valid while d+8 <= 63 (d <= 55)
    STEP(0, true)  STEP(1, true)  STEP(2, true)  STEP(3, true)
    STEP(4, false) STEP(5, false) STEP(6, false) STEP(7, false)
    STEP(8, false) STEP(9, false) STEP(10, false) STEP(11, false)
#undef STEP

    // Block reduction: 5 warps of 32
    __shared__ float red[5];
#pragma unroll
    for (int off = 16; off > 0; off >>= 1)
        acc += __shfl_down_sync(0xffffffffu, acc, off);
    if ((threadIdx.x & 31) == 0) red[threadIdx.x >> 5] = acc;
    __syncthreads();
    if (threadIdx.x == 0) {
        float s = red[0] + red[1] + red[2] + red[3] + red[4];
        atomicAdd(&g_acc[c], s);
    }
}

// Reads the per-channel sums, writes the loss, and re-zeroes g_acc so the
// next call (graph replay) starts clean. First call relies on .bss zero-init.
__global__ void final_kernel(float* __restrict__ out) {
    int c = threadIdx.x;
    if (c < C_) {
        out[c] = 1.f - g_acc[c] * (1.f / (float)NVOX_PER_CH);
        g_acc[c] = 0.f;
    }
}

extern "C" void kernel_launch(void* const* d_in, const int* in_sizes, int n_in,
                              void* d_out, int out_size) {
    (void)in_sizes; (void)n_in; (void)out_size;
    const float* img1 = (const float*)d_in[0];
    const float* img2 = (const float*)d_in[1];
    float* out = (float*)d_out;

    dim3 gA(W_ / TS, H_ / TS, NSLICE);  // (5, 5, 512)
    passA_kernel<<<gA, 256>>>(img1, img2);
    passB_kernel<<<BC_ * H_, 160>>>();
    final_kernel<<<1, 32>>>(out);
}